// round 12
// baseline (speedup 1.0000x reference)
#include <cuda_runtime.h>
#include <math.h>

// x: [16, 4, 2048, 257] fp32 -> BM=64 series-groups, T=2048, F=257
#define BM_      64
#define T_       2048
#define F_       257
#define CLEN     32                 // frames per chunk
#define NCH      (T_ / CLEN)        // 64 chunks per series
#define GRID_    (BM_ * NCH)        // 4096 blocks = 2^12 per launch
#define NTHREADS 288                // 9 warps; threads [0,257) active
#define EPS_     1e-6f

// Published prefix-EMA tail per (bm, chunk, f). NO reset kernel: values are
// epoch-parity encoded (even epoch: -(m+1) <= -1, odd epoch: m >= 0). Launches
// serialize, so stale entries are always opposite-parity -> rejected. Initial
// zero-init memory is rejected by the even-parity predicate (needs v <= -1).
__device__ float        g_mend[BM_ * NCH * F_];
__device__ unsigned int g_ticket;     // monotonically increasing across launches

__device__ __forceinline__ float ld_relaxed_gpu(const float* p) {
    float v;
    asm volatile("ld.relaxed.gpu.f32 %0, [%1];" : "=f"(v) : "l"(p));
    return v;
}
__device__ __forceinline__ void st_relaxed_gpu(float* p, float v) {
    asm volatile("st.relaxed.gpu.f32 [%0], %1;" :: "l"(p), "f"(v));
}
__device__ __forceinline__ float lg2f(float v) { float r; asm("lg2.approx.f32 %0, %1;" : "=f"(r) : "f"(v)); return r; }
__device__ __forceinline__ float ex2f(float v) { float r; asm("ex2.approx.f32 %0, %1;" : "=f"(r) : "f"(v)); return r; }
__device__ __forceinline__ float rsqf(float v) { float r; asm("rsqrt.approx.f32 %0, %1;" : "=f"(r) : "f"(v)); return r; }

__global__ __launch_bounds__(NTHREADS, 5)
void pcen_kernel(const float* __restrict__ x,
                 const float* __restrict__ s_p,
                 const float* __restrict__ alpha_p,
                 const float* __restrict__ delta_p,
                 const float* __restrict__ r_p,
                 float* __restrict__ out) {
    // Per-frame local EMA stash; each thread touches only its own f column
    // -> no __syncthreads needed for it. 32.9 KB static smem.
    __shared__ float sml[CLEN][F_];

    // Ticket-order virtualization (deadlock-free: waiter's predecessor always
    // holds a smaller ticket). Epoch = ticket / 4096 (exactly GRID_ per launch).
    __shared__ unsigned int s_vb;
    if (threadIdx.x == 0) s_vb = atomicAdd(&g_ticket, 1u);
    __syncthreads();
    const unsigned int tk = s_vb;
    const int vb     = (int)(tk & (GRID_ - 1));
    const int parity = (int)((tk >> 12) & 1u);
    const int bm = vb & (BM_ - 1);          // fast-varying: all 64 chains advance per wave
    const int c  = vb >> 6;                 // chunk index along T

    const int f = threadIdx.x;
    if (f >= F_) return;

    const float s     = s_p[0];
    const float alpha = alpha_p[0];
    const float delta = delta_p[0];
    const float r     = r_p[0];
    const float oms   = 1.0f - s;

    const size_t base = ((size_t)bm * T_ + (size_t)c * CLEN) * F_ + f;
    const float* xp = x + base;

    // ---- Phase A: stream x once; zero-init local EMA; stash per-frame m_loc ----
    float m;
    {
        const float x0 = __ldg(xp);
        m = (c == 0) ? x0 : (s * x0);       // chunk 0: exact M_0 = x_0
        sml[0][f] = m;
#pragma unroll
        for (int i = 1; i < CLEN; i++) {
            m = fmaf(oms, m, s * __ldg(xp + (size_t)i * F_));
            sml[i][f] = m;
        }
    }

    // ---- Phase B: chain combine via per-f spin (parity-encoded, no reset) ----
    float m_in = 0.0f;
    if (c > 0) {
        const float* prev = &g_mend[((size_t)bm * NCH + (size_t)(c - 1)) * F_ + f];
        float v;
        if (parity == 0) {                  // predecessor encoded as -(m+1) <= -1
            do { v = ld_relaxed_gpu(prev); } while (v > -1.0f);
            m_in = -v - 1.0f;
        } else {                            // predecessor encoded as m >= 0
            do { v = ld_relaxed_gpu(prev); } while (v < 0.0f);
            m_in = v;
        }
        float D = oms;                      // (1-s)^32 by repeated squaring
#pragma unroll
        for (int k = 0; k < 5; k++) D *= D;
        m = fmaf(D, m_in, m);               // full prefix tail
    }
    {
        const float enc = (parity == 0) ? (-(m + 1.0f)) : m;
        st_relaxed_gpu(&g_mend[((size_t)bm * NCH + (size_t)c) * F_ + f], enc);
    }

    // ---- Phase C: dependence-free reconstruction + PCEN nonlinearity ----
    // mm_i = m_loc_i + oms^(i+1) * m_in   (exact by linearity; m_in=0 for c==0)
    const bool  half = (r == 0.5f);
    const float dr   = half ? sqrtf(delta) : ex2f(r * lg2f(delta));
    const float oms2 = oms * oms;
    const float oms3 = oms2 * oms;
    const float oms4 = oms2 * oms2;

    float* op = out + base;
    float eg = oms * m_in;                  // oms^(4g+1) * m_in, updated per group
#pragma unroll 2
    for (int g = 0; g < CLEN / 4; g++) {
        const size_t o0 = (size_t)(4 * g) * F_;
        float xv0 = __ldcs(xp + o0);
        float xv1 = __ldcs(xp + o0 + F_);
        float xv2 = __ldcs(xp + o0 + 2 * F_);
        float xv3 = __ldcs(xp + o0 + 3 * F_);
        float mm0 = eg               + sml[4 * g + 0][f];
        float mm1 = fmaf(eg, oms,      sml[4 * g + 1][f]);
        float mm2 = fmaf(eg, oms2,     sml[4 * g + 2][f]);
        float mm3 = fmaf(eg, oms3,     sml[4 * g + 3][f]);
        eg *= oms4;

        float pw0 = ex2f(-alpha * lg2f(mm0 + EPS_));
        float pw1 = ex2f(-alpha * lg2f(mm1 + EPS_));
        float pw2 = ex2f(-alpha * lg2f(mm2 + EPS_));
        float pw3 = ex2f(-alpha * lg2f(mm3 + EPS_));
        float u0 = fmaf(xv0, pw0, delta);
        float u1 = fmaf(xv1, pw1, delta);
        float u2 = fmaf(xv2, pw2, delta);
        float u3 = fmaf(xv3, pw3, delta);
        float q0 = half ? fmaf(u0, rsqf(u0), -dr) : (ex2f(r * lg2f(u0)) - dr);
        float q1 = half ? fmaf(u1, rsqf(u1), -dr) : (ex2f(r * lg2f(u1)) - dr);
        float q2 = half ? fmaf(u2, rsqf(u2), -dr) : (ex2f(r * lg2f(u2)) - dr);
        float q3 = half ? fmaf(u3, rsqf(u3), -dr) : (ex2f(r * lg2f(u3)) - dr);
        __stcs(op + o0,          q0);
        __stcs(op + o0 + F_,     q1);
        __stcs(op + o0 + 2 * F_, q2);
        __stcs(op + o0 + 3 * F_, q3);
    }
}

extern "C" void kernel_launch(void* const* d_in, const int* in_sizes, int n_in,
                              void* d_out, int out_size) {
    const float* x     = (const float*)d_in[0];
    const float* s     = (const float*)d_in[1];
    const float* alpha = (const float*)d_in[2];
    const float* delta = (const float*)d_in[3];
    const float* r     = (const float*)d_in[4];
    float* out = (float*)d_out;

    (void)in_sizes; (void)n_in; (void)out_size;

    pcen_kernel<<<GRID_, NTHREADS>>>(x, s, alpha, delta, r, out);
}